// round 14
// baseline (speedup 1.0000x reference)
#include <cuda_runtime.h>

#define NN   50000
#define NSEG 150000
#define NT   256
#define EMAX 4500000

// ---------------- scratch (static device globals; no allocs) ----------------
__device__ int   g_is64;                 // 1 if edge indices are int64, 0 if int32
__device__ int   g_cnt[6 * NN];          // [2r]=deg_out(src), [2r+1]=deg_in(dst)
__device__ int2  g_edges[EMAX + 8];      // compacted (src + r*NN, dst + r*NN), padded
__device__ float g_h1 [NSEG * 16];       // per-relation scaled layer-1 features
__device__ float g_m  [NSEG * 16];       // per-relation aggregation buffers
__device__ float g_s  [NSEG];            // per-relation scalar layer-2 messages
__device__ float g_o2 [NSEG];            // per-relation scalar aggregation

__device__ __forceinline__ float rs_of(int cnt) {
    return rsqrtf((float)(cnt > 0 ? cnt : 1));
}

// ---------------- init: dtype detect (block 0) + zero counters + pad --------
__global__ void k_init(const unsigned* __restrict__ p, int n) {
    if (blockIdx.x == 0) {
        __shared__ int found;
        if (threadIdx.x == 0) found = 0;
        __syncthreads();
        int f = 0;
        for (int j = threadIdx.x; j < n; j += blockDim.x)
            if (p[2 * j + 1] != 0u) f = 1;
        if (f) atomicOr(&found, 1);
        __syncthreads();
        if (threadIdx.x == 0) g_is64 = found ? 0 : 1;
    }
    int i = blockIdx.x * blockDim.x + threadIdx.x;
    for (int k = i; k < 6 * NN; k += gridDim.x * blockDim.x)
        g_cnt[k] = 0;
    if (i < 8) g_edges[EMAX + i] = make_int2(0, 0);
}

// ------- degrees + compaction: 2 edges/thread, vector idx loads -------------
__global__ void k_degc(const void* __restrict__ src, const void* __restrict__ dst,
                       int E, int r, int eoff) {
    int t = blockIdx.x * blockDim.x + threadIdx.x;
    int e0 = t * 2;
    if (e0 >= E) return;
    bool two = (e0 + 1 < E);
    int s0, d0, s1 = 0, d1 = 0;
    if (g_is64) {
        int4 sv = __ldg((const int4*)((const long long*)src + e0));
        int4 dv = __ldg((const int4*)((const long long*)dst + e0));
        s0 = sv.x; s1 = sv.z; d0 = dv.x; d1 = dv.z;
    } else {
        int2 sv = __ldg((const int2*)((const int*)src + e0));
        int2 dv = __ldg((const int2*)((const int*)dst + e0));
        s0 = sv.x; s1 = sv.y; d0 = dv.x; d1 = dv.y;
    }
    int b = r * NN;
    atomicAdd(&g_cnt[(2 * r)     * NN + s0], 1);
    atomicAdd(&g_cnt[(2 * r + 1) * NN + d0], 1);
    if (two) {
        atomicAdd(&g_cnt[(2 * r)     * NN + s1], 1);
        atomicAdd(&g_cnt[(2 * r + 1) * NN + d1], 1);
    }
    int p0 = eoff + e0;
    if (two && ((p0 & 1) == 0)) {
        *(int4*)&g_edges[p0] = make_int4(b + s0, b + d0, b + s1, b + d1);
    } else {
        g_edges[p0] = make_int2(b + s0, b + d0);
        if (two) g_edges[p0 + 1] = make_int2(b + s1, b + d1);
    }
}

// ---------------- layer 1: per-node transform (and zero g_m) ----------------
__global__ void k_layer1_node(const float* __restrict__ x, const float* __restrict__ W1) {
    __shared__ float sW[3 * 32 * 16];
    for (int i = threadIdx.x; i < 1536; i += blockDim.x) sW[i] = W1[i];
    __syncthreads();
    int n = blockIdx.x * blockDim.x + threadIdx.x;
    if (n >= NN) return;
    float xv[32];
    #pragma unroll
    for (int j = 0; j < 8; j++) {
        float4 v = __ldg((const float4*)(x + (size_t)n * 32) + j);
        xv[4*j] = v.x; xv[4*j+1] = v.y; xv[4*j+2] = v.z; xv[4*j+3] = v.w;
    }
    #pragma unroll
    for (int r = 0; r < 3; r++) {
        float a = rs_of(g_cnt[(2 * r) * NN + n]);
        float y[16];
        #pragma unroll
        for (int f = 0; f < 16; f++) y[f] = 0.f;
        #pragma unroll
        for (int j = 0; j < 32; j++) {
            float xj = xv[j];
            #pragma unroll
            for (int f = 0; f < 16; f++)
                y[f] += xj * sW[r * 512 + j * 16 + f];
        }
        float* hp = &g_h1[(size_t)(r * NN + n) * 16];
        float* mp = &g_m [(size_t)(r * NN + n) * 16];
        #pragma unroll
        for (int f = 0; f < 16; f += 4) {
            *(float4*)(hp + f) = make_float4(a*y[f], a*y[f+1], a*y[f+2], a*y[f+3]);
            *(float4*)(mp + f) = make_float4(0.f, 0.f, 0.f, 0.f);
        }
    }
}

#define RED16(dseg, vv) do {                                                   \
    float* mp_ = &g_m[(size_t)(dseg) * 16 + c * 4];                            \
    asm volatile("red.global.add.v4.f32 [%0], {%1, %2, %3, %4};"               \
                 :: "l"(mp_), "f"((vv).x), "f"((vv).y), "f"((vv).z), "f"((vv).w) \
                 : "memory");                                                  \
} while (0)

// ---- layer 1 scatter: 4-lane chunk split, 8 EDGES PER THREAD ---------------
__global__ void k_scatter16(int Etot) {
    long long t = (long long)blockIdx.x * blockDim.x + threadIdx.x;
    int c = (int)(t & 3);
    long long g = t >> 2;
    long long e0 = g << 3;
    if (e0 >= Etot) return;
    const int4* ep = (const int4*)g_edges;
    int4 q0 = __ldg(ep + 4 * g);
    int4 q1 = __ldg(ep + 4 * g + 1);
    int4 q2 = __ldg(ep + 4 * g + 2);
    int4 q3 = __ldg(ep + 4 * g + 3);
    long long rem = Etot - e0;
    const float4 z = make_float4(0.f, 0.f, 0.f, 0.f);
    float4 v0 =            __ldg((const float4*)&g_h1[(size_t)q0.x * 16] + c);
    float4 v1 = rem > 1 ?  __ldg((const float4*)&g_h1[(size_t)q0.z * 16] + c) : z;
    float4 v2 = rem > 2 ?  __ldg((const float4*)&g_h1[(size_t)q1.x * 16] + c) : z;
    float4 v3 = rem > 3 ?  __ldg((const float4*)&g_h1[(size_t)q1.z * 16] + c) : z;
    float4 v4 = rem > 4 ?  __ldg((const float4*)&g_h1[(size_t)q2.x * 16] + c) : z;
    float4 v5 = rem > 5 ?  __ldg((const float4*)&g_h1[(size_t)q2.z * 16] + c) : z;
    float4 v6 = rem > 6 ?  __ldg((const float4*)&g_h1[(size_t)q3.x * 16] + c) : z;
    float4 v7 = rem > 7 ?  __ldg((const float4*)&g_h1[(size_t)q3.z * 16] + c) : z;
    RED16(q0.y, v0);
    if (rem > 1) RED16(q0.w, v1);
    if (rem > 2) RED16(q1.y, v2);
    if (rem > 3) RED16(q1.w, v3);
    if (rem > 4) RED16(q2.y, v4);
    if (rem > 5) RED16(q2.w, v5);
    if (rem > 6) RED16(q3.y, v6);
    if (rem > 7) RED16(q3.w, v7);
}

// ---------------- combine + relu + layer-2 node transform (zero g_o2) -------
__global__ void k_combine(const float* __restrict__ b1, const float* __restrict__ W2) {
    __shared__ float sW2[48], sb1[48];
    if (threadIdx.x < 48) {
        sW2[threadIdx.x] = W2[threadIdx.x];
        sb1[threadIdx.x] = b1[threadIdx.x];
    }
    __syncthreads();
    int n = blockIdx.x * blockDim.x + threadIdx.x;
    if (n >= NN) return;
    float acc[16];
    #pragma unroll
    for (int f = 0; f < 16; f++) acc[f] = 0.f;
    #pragma unroll
    for (int r = 0; r < 3; r++) {
        float ain = rs_of(g_cnt[(2 * r + 1) * NN + n]);
        const float* mp = &g_m[(size_t)(r * NN + n) * 16];
        #pragma unroll
        for (int f = 0; f < 16; f += 4) {
            float4 v = *(const float4*)(mp + f);
            acc[f]   += v.x * ain + sb1[r*16 + f];
            acc[f+1] += v.y * ain + sb1[r*16 + f + 1];
            acc[f+2] += v.z * ain + sb1[r*16 + f + 2];
            acc[f+3] += v.w * ain + sb1[r*16 + f + 3];
        }
    }
    #pragma unroll
    for (int f = 0; f < 16; f++) acc[f] = fmaxf(acc[f], 0.f);
    #pragma unroll
    for (int r = 0; r < 3; r++) {
        float aout = rs_of(g_cnt[(2 * r) * NN + n]);
        float dot = 0.f;
        #pragma unroll
        for (int f = 0; f < 16; f++) dot += acc[f] * sW2[r*16 + f];
        g_s [r * NN + n] = aout * dot;
        g_o2[r * NN + n] = 0.f;
    }
}

// ---- layer 2: scalar edge scatter, 4 edges/thread --------------------------
__global__ void k_scatter1(int Etot) {
    int t = blockIdx.x * blockDim.x + threadIdx.x;
    int e0 = t << 2;
    if (e0 >= Etot) return;
    const int4* ep = (const int4*)g_edges;
    int4 q0 = __ldg(ep + 2 * t);
    int4 q1 = __ldg(ep + 2 * t + 1);
    int rem = Etot - e0;
    float v0 = __ldg(&g_s[q0.x]);
    float v1 = (rem > 1) ? __ldg(&g_s[q0.z]) : 0.f;
    float v2 = (rem > 2) ? __ldg(&g_s[q1.x]) : 0.f;
    float v3 = (rem > 3) ? __ldg(&g_s[q1.z]) : 0.f;
    atomicAdd(&g_o2[q0.y], v0);
    if (rem > 1) atomicAdd(&g_o2[q0.w], v1);
    if (rem > 2) atomicAdd(&g_o2[q1.y], v2);
    if (rem > 3) atomicAdd(&g_o2[q1.w], v3);
}

// ---------------- final ----------------
__global__ void k_final(float* __restrict__ out, const float* __restrict__ b2) {
    int n = blockIdx.x * blockDim.x + threadIdx.x;
    if (n >= NN) return;
    float o = __ldg(b2) + __ldg(b2 + 1) + __ldg(b2 + 2);
    #pragma unroll
    for (int r = 0; r < 3; r++)
        o += g_o2[r * NN + n] * rs_of(g_cnt[(2 * r + 1) * NN + n]);
    out[n] = o;
}

// ---------------- host ----------------
extern "C" void kernel_launch(void* const* d_in, const int* in_sizes, int n_in,
                              void* d_out, int out_size) {
    const float* x  = (const float*)d_in[0];
    const void*  src[3] = { d_in[1], d_in[3], d_in[5] };
    const void*  dst[3] = { d_in[2], d_in[4], d_in[6] };
    int          E[3]   = { in_sizes[1], in_sizes[3], in_sizes[5] };
    const float* W1 = (const float*)d_in[7];
    const float* b1 = (const float*)d_in[8];
    const float* W2 = (const float*)d_in[9];
    const float* b2 = (const float*)d_in[10];
    float*       out = (float*)d_out;

    int Etot = E[0] + E[1] + E[2];
    if (Etot > EMAX) Etot = EMAX;

    int nprobe = E[0] < 2048 ? E[0] : 2048;
    // launch 0: init (detect + zero)
    k_init<<<(6 * NN + NT - 1) / NT, NT>>>((const unsigned*)d_in[1], nprobe);

    // launches 1-3: degc
    int eoff = 0;
    for (int r = 0; r < 3; r++) {
        int thr = (E[r] + 1) / 2;
        k_degc<<<(thr + NT - 1) / NT, NT>>>(src[r], dst[r], E[r], r, eoff);
        eoff += E[r];
    }

    // launch 4: layer1
    k_layer1_node<<<(NN + NT - 1) / NT, NT>>>(x, W1);

    // launch 5: scatter16  (ncu -s 5 -c 1 captures THIS)
    {
        long long groups = ((long long)Etot + 7) / 8;
        long long work = groups * 4;
        int blocks = (int)((work + NT - 1) / NT);
        k_scatter16<<<blocks, NT>>>(Etot);
    }

    // launches 6-8
    k_combine<<<(NN + NT - 1) / NT, NT>>>(b1, W2);
    {
        int thr = (Etot + 3) / 4;
        k_scatter1<<<(thr + NT - 1) / NT, NT>>>(Etot);
    }
    k_final<<<(NN + NT - 1) / NT, NT>>>(out, b2);
}

// round 16
// speedup vs baseline: 1.0214x; 1.0214x over previous
#include <cuda_runtime.h>

#define NN   50000
#define NSEG 150000
#define NT   256
#define EMAX 4500000

// ---------------- scratch (static device globals; no allocs) ----------------
__device__ int   g_is64;                 // 1 if edge indices are int64, 0 if int32
__device__ int   g_cnt[6 * NN];          // [2r]=deg_out(src), [2r+1]=deg_in(dst)
__device__ int2  g_edges[EMAX + 8];      // compacted (src + r*NN, dst + r*NN), padded
__device__ float g_h1 [NSEG * 16];       // per-relation scaled layer-1 features
__device__ float g_m  [NSEG * 16];       // per-relation aggregation buffers
__device__ float g_s  [NSEG];            // per-relation scalar layer-2 messages
__device__ float g_o2 [NSEG];            // per-relation scalar aggregation

__device__ __forceinline__ float rs_of(int cnt) {
    return rsqrtf((float)(cnt > 0 ? cnt : 1));
}

// ---------------- init: dtype detect (block 0) + zero counters + pad --------
__global__ void k_init(const unsigned* __restrict__ p, int n) {
    if (blockIdx.x == 0) {
        __shared__ int found;
        if (threadIdx.x == 0) found = 0;
        __syncthreads();
        int f = 0;
        for (int j = threadIdx.x; j < n; j += blockDim.x)
            if (p[2 * j + 1] != 0u) f = 1;
        if (f) atomicOr(&found, 1);
        __syncthreads();
        if (threadIdx.x == 0) g_is64 = found ? 0 : 1;
    }
    int i = blockIdx.x * blockDim.x + threadIdx.x;
    for (int k = i; k < 6 * NN; k += gridDim.x * blockDim.x)
        g_cnt[k] = 0;
    if (i < 8) g_edges[EMAX + i] = make_int2(0, 0);
}

// ------- degrees + compaction: ONE launch, gridDim.y = relation -------------
// 2 edges/thread, vectorized idx loads. Oversized x-slices return early.
__global__ void k_degc_all(const void* __restrict__ s0p, const void* __restrict__ d0p,
                           const void* __restrict__ s1p, const void* __restrict__ d1p,
                           const void* __restrict__ s2p, const void* __restrict__ d2p,
                           int E0, int E1, int E2) {
    int r = blockIdx.y;
    const void* src = (r == 0) ? s0p : (r == 1) ? s1p : s2p;
    const void* dst = (r == 0) ? d0p : (r == 1) ? d1p : d2p;
    int E    = (r == 0) ? E0 : (r == 1) ? E1 : E2;
    int eoff = (r == 0) ? 0  : (r == 1) ? E0 : E0 + E1;

    int t = blockIdx.x * blockDim.x + threadIdx.x;
    int e0 = t * 2;
    if (e0 >= E) return;
    bool two = (e0 + 1 < E);
    int s0, d0, s1 = 0, d1 = 0;
    if (g_is64) {
        int4 sv = __ldg((const int4*)((const long long*)src + e0));
        int4 dv = __ldg((const int4*)((const long long*)dst + e0));
        s0 = sv.x; s1 = sv.z; d0 = dv.x; d1 = dv.z;
    } else {
        int2 sv = __ldg((const int2*)((const int*)src + e0));
        int2 dv = __ldg((const int2*)((const int*)dst + e0));
        s0 = sv.x; s1 = sv.y; d0 = dv.x; d1 = dv.y;
    }
    int b = r * NN;
    atomicAdd(&g_cnt[(2 * r)     * NN + s0], 1);
    atomicAdd(&g_cnt[(2 * r + 1) * NN + d0], 1);
    if (two) {
        atomicAdd(&g_cnt[(2 * r)     * NN + s1], 1);
        atomicAdd(&g_cnt[(2 * r + 1) * NN + d1], 1);
    }
    int p0 = eoff + e0;
    if (two && ((p0 & 1) == 0)) {
        *(int4*)&g_edges[p0] = make_int4(b + s0, b + d0, b + s1, b + d1);
    } else {
        g_edges[p0] = make_int2(b + s0, b + d0);
        if (two) g_edges[p0 + 1] = make_int2(b + s1, b + d1);
    }
}

// ---------------- layer 1: per-node transform (and zero g_m) ----------------
__global__ void k_layer1_node(const float* __restrict__ x, const float* __restrict__ W1) {
    __shared__ float sW[3 * 32 * 16];
    for (int i = threadIdx.x; i < 1536; i += blockDim.x) sW[i] = W1[i];
    __syncthreads();
    int n = blockIdx.x * blockDim.x + threadIdx.x;
    if (n >= NN) return;
    float xv[32];
    #pragma unroll
    for (int j = 0; j < 8; j++) {
        float4 v = __ldg((const float4*)(x + (size_t)n * 32) + j);
        xv[4*j] = v.x; xv[4*j+1] = v.y; xv[4*j+2] = v.z; xv[4*j+3] = v.w;
    }
    #pragma unroll
    for (int r = 0; r < 3; r++) {
        float a = rs_of(g_cnt[(2 * r) * NN + n]);
        float y[16];
        #pragma unroll
        for (int f = 0; f < 16; f++) y[f] = 0.f;
        #pragma unroll
        for (int j = 0; j < 32; j++) {
            float xj = xv[j];
            #pragma unroll
            for (int f = 0; f < 16; f++)
                y[f] += xj * sW[r * 512 + j * 16 + f];
        }
        float* hp = &g_h1[(size_t)(r * NN + n) * 16];
        float* mp = &g_m [(size_t)(r * NN + n) * 16];
        #pragma unroll
        for (int f = 0; f < 16; f += 4) {
            *(float4*)(hp + f) = make_float4(a*y[f], a*y[f+1], a*y[f+2], a*y[f+3]);
            *(float4*)(mp + f) = make_float4(0.f, 0.f, 0.f, 0.f);
        }
    }
}

// ---- layer 1 scatter: 4-lane chunk split, 4 EDGES PER THREAD (R13 best) ----
__global__ void k_scatter16(int Etot) {
    long long t = (long long)blockIdx.x * blockDim.x + threadIdx.x;
    int c = (int)(t & 3);
    long long g = t >> 2;
    int e0 = (int)(g << 2);
    if (e0 >= Etot) return;
    const int4* ep = (const int4*)g_edges;
    int4 q0 = __ldg(ep + 2 * g);        // edges e0, e0+1
    int4 q1 = __ldg(ep + 2 * g + 1);    // edges e0+2, e0+3 (padded region safe)
    int rem = Etot - e0;                // >= 1

    const float4 z = make_float4(0.f, 0.f, 0.f, 0.f);
    float4 v0 =             __ldg((const float4*)&g_h1[(size_t)q0.x * 16] + c);
    float4 v1 = (rem > 1) ? __ldg((const float4*)&g_h1[(size_t)q0.z * 16] + c) : z;
    float4 v2 = (rem > 2) ? __ldg((const float4*)&g_h1[(size_t)q1.x * 16] + c) : z;
    float4 v3 = (rem > 3) ? __ldg((const float4*)&g_h1[(size_t)q1.z * 16] + c) : z;

    {
        float* mp = &g_m[(size_t)q0.y * 16 + c * 4];
        asm volatile("red.global.add.v4.f32 [%0], {%1, %2, %3, %4};"
                     :: "l"(mp), "f"(v0.x), "f"(v0.y), "f"(v0.z), "f"(v0.w) : "memory");
    }
    if (rem > 1) {
        float* mp = &g_m[(size_t)q0.w * 16 + c * 4];
        asm volatile("red.global.add.v4.f32 [%0], {%1, %2, %3, %4};"
                     :: "l"(mp), "f"(v1.x), "f"(v1.y), "f"(v1.z), "f"(v1.w) : "memory");
    }
    if (rem > 2) {
        float* mp = &g_m[(size_t)q1.y * 16 + c * 4];
        asm volatile("red.global.add.v4.f32 [%0], {%1, %2, %3, %4};"
                     :: "l"(mp), "f"(v2.x), "f"(v2.y), "f"(v2.z), "f"(v2.w) : "memory");
    }
    if (rem > 3) {
        float* mp = &g_m[(size_t)q1.w * 16 + c * 4];
        asm volatile("red.global.add.v4.f32 [%0], {%1, %2, %3, %4};"
                     :: "l"(mp), "f"(v3.x), "f"(v3.y), "f"(v3.z), "f"(v3.w) : "memory");
    }
}

// ---------------- combine + relu + layer-2 node transform (zero g_o2) -------
__global__ void k_combine(const float* __restrict__ b1, const float* __restrict__ W2) {
    __shared__ float sW2[48], sb1[48];
    if (threadIdx.x < 48) {
        sW2[threadIdx.x] = W2[threadIdx.x];
        sb1[threadIdx.x] = b1[threadIdx.x];
    }
    __syncthreads();
    int n = blockIdx.x * blockDim.x + threadIdx.x;
    if (n >= NN) return;
    float acc[16];
    #pragma unroll
    for (int f = 0; f < 16; f++) acc[f] = 0.f;
    #pragma unroll
    for (int r = 0; r < 3; r++) {
        float ain = rs_of(g_cnt[(2 * r + 1) * NN + n]);
        const float* mp = &g_m[(size_t)(r * NN + n) * 16];
        #pragma unroll
        for (int f = 0; f < 16; f += 4) {
            float4 v = *(const float4*)(mp + f);
            acc[f]   += v.x * ain + sb1[r*16 + f];
            acc[f+1] += v.y * ain + sb1[r*16 + f + 1];
            acc[f+2] += v.z * ain + sb1[r*16 + f + 2];
            acc[f+3] += v.w * ain + sb1[r*16 + f + 3];
        }
    }
    #pragma unroll
    for (int f = 0; f < 16; f++) acc[f] = fmaxf(acc[f], 0.f);
    #pragma unroll
    for (int r = 0; r < 3; r++) {
        float aout = rs_of(g_cnt[(2 * r) * NN + n]);
        float dot = 0.f;
        #pragma unroll
        for (int f = 0; f < 16; f++) dot += acc[f] * sW2[r*16 + f];
        g_s [r * NN + n] = aout * dot;
        g_o2[r * NN + n] = 0.f;
    }
}

// ---- layer 2: scalar edge scatter, 4 edges/thread --------------------------
__global__ void k_scatter1(int Etot) {
    int t = blockIdx.x * blockDim.x + threadIdx.x;
    int e0 = t << 2;
    if (e0 >= Etot) return;
    const int4* ep = (const int4*)g_edges;
    int4 q0 = __ldg(ep + 2 * t);
    int4 q1 = __ldg(ep + 2 * t + 1);
    int rem = Etot - e0;
    float v0 = __ldg(&g_s[q0.x]);
    float v1 = (rem > 1) ? __ldg(&g_s[q0.z]) : 0.f;
    float v2 = (rem > 2) ? __ldg(&g_s[q1.x]) : 0.f;
    float v3 = (rem > 3) ? __ldg(&g_s[q1.z]) : 0.f;
    atomicAdd(&g_o2[q0.y], v0);
    if (rem > 1) atomicAdd(&g_o2[q0.w], v1);
    if (rem > 2) atomicAdd(&g_o2[q1.y], v2);
    if (rem > 3) atomicAdd(&g_o2[q1.w], v3);
}

// ---------------- final ----------------
__global__ void k_final(float* __restrict__ out, const float* __restrict__ b2) {
    int n = blockIdx.x * blockDim.x + threadIdx.x;
    if (n >= NN) return;
    float o = __ldg(b2) + __ldg(b2 + 1) + __ldg(b2 + 2);
    #pragma unroll
    for (int r = 0; r < 3; r++)
        o += g_o2[r * NN + n] * rs_of(g_cnt[(2 * r + 1) * NN + n]);
    out[n] = o;
}

// ---------------- host ----------------
extern "C" void kernel_launch(void* const* d_in, const int* in_sizes, int n_in,
                              void* d_out, int out_size) {
    const float* x  = (const float*)d_in[0];
    int          E[3] = { in_sizes[1], in_sizes[3], in_sizes[5] };
    const float* W1 = (const float*)d_in[7];
    const float* b1 = (const float*)d_in[8];
    const float* W2 = (const float*)d_in[9];
    const float* b2 = (const float*)d_in[10];
    float*       out = (float*)d_out;

    int Etot = E[0] + E[1] + E[2];
    if (Etot > EMAX) Etot = EMAX;

    int nprobe = E[0] < 2048 ? E[0] : 2048;
    // launch 0: init (detect + zero)
    k_init<<<(6 * NN + NT - 1) / NT, NT>>>((const unsigned*)d_in[1], nprobe);

    // launch 1: fused degc over all 3 relations (gridDim.y = relation)
    {
        int Emax3 = E[0] > E[1] ? (E[0] > E[2] ? E[0] : E[2])
                                : (E[1] > E[2] ? E[1] : E[2]);
        int xblocks = ((Emax3 + 1) / 2 + NT - 1) / NT;
        dim3 grid(xblocks, 3, 1);
        k_degc_all<<<grid, NT>>>(d_in[1], d_in[2], d_in[3], d_in[4],
                                 d_in[5], d_in[6], E[0], E[1], E[2]);
    }

    // launch 2: layer1
    k_layer1_node<<<(NN + NT - 1) / NT, NT>>>(x, W1);

    // launch 3: scatter16  (this is the slot ncu captured last round)
    {
        long long groups = ((long long)Etot + 3) / 4;
        long long work = groups * 4;
        int blocks = (int)((work + NT - 1) / NT);
        k_scatter16<<<blocks, NT>>>(Etot);
    }

    // launches 4-6
    k_combine<<<(NN + NT - 1) / NT, NT>>>(b1, W2);
    {
        int thr = (Etot + 3) / 4;
        k_scatter1<<<(thr + NT - 1) / NT, NT>>>(Etot);
    }
    k_final<<<(NN + NT - 1) / NT, NT>>>(out, b2);
}